// round 1
// baseline (speedup 1.0000x reference)
#include <cuda_runtime.h>
#include <cuda_bf16.h>

#define BB   16
#define TT   12
#define NN   307
#define DD   64
#define TM   (TT*NN)      // 3684
#define NT   4            // n-rows per attention block
#define WMAX 928          // max kept elements (kk-1 = 920)
#define SCALE 0.125f      // 1/sqrt(64)

// ---------------- scratch (no runtime allocation allowed) ----------------
__device__ float g_xn[(size_t)BB*TT*NN*DD];   // layernormed x
__device__ float g_k [(size_t)BB*TT*NN*DD];   // K projection
__device__ float g_q [(size_t)BB*NN*DD];      // Q projection (from t = T-1)
__device__ float g_h [(size_t)BB*NN*DD];      // attention output + residual

__device__ __forceinline__ unsigned mono(float f) {
    unsigned u = __float_as_uint(f);
    return (u & 0x80000000u) ? ~u : (u | 0x80000000u);
}

// ---------------- K1: LayerNorm over d=64, one warp per row ----------------
__global__ void ln_kernel(const float* __restrict__ x,
                          const float* __restrict__ g,
                          const float* __restrict__ b, int rows) {
    int row  = blockIdx.x * 8 + (threadIdx.x >> 5);
    int lane = threadIdx.x & 31;
    if (row >= rows) return;
    const float2* xr = (const float2*)(x + (size_t)row * DD);
    float2 v = xr[lane];
    float s = v.x + v.y;
    #pragma unroll
    for (int o = 16; o > 0; o >>= 1) s += __shfl_xor_sync(0xFFFFFFFFu, s, o);
    float mu = s * (1.0f / DD);
    float dx = v.x - mu, dy = v.y - mu;
    float q = dx * dx + dy * dy;
    #pragma unroll
    for (int o = 16; o > 0; o >>= 1) q += __shfl_xor_sync(0xFFFFFFFFu, q, o);
    float rstd = rsqrtf(q * (1.0f / DD) + 1e-5f);
    float2 gg = ((const float2*)g)[lane];
    float2 bv = ((const float2*)b)[lane];
    float2 ov;
    ov.x = dx * rstd * gg.x + bv.x;
    ov.y = dy * rstd * gg.y + bv.y;
    ((float2*)(g_xn + (size_t)row * DD))[lane] = ov;
}

// ---------------- K2: K = x_ @ k_w.T + k_b ----------------
__global__ void k_kernel(const float* __restrict__ W,
                         const float* __restrict__ bias, int rows) {
    __shared__ float xs[4][DD];
    int r = threadIdx.x >> 6, j = threadIdx.x & 63;
    int row = blockIdx.x * 4 + r;
    if (row < rows) xs[r][j] = g_xn[(size_t)row * DD + j];
    __syncthreads();
    if (row >= rows) return;
    float acc = bias[j];
    const float4* w4 = (const float4*)(W + (size_t)j * DD);
    #pragma unroll
    for (int i = 0; i < 16; i++) {
        float4 w = w4[i];
        acc += w.x * xs[r][4*i] + w.y * xs[r][4*i+1]
             + w.z * xs[r][4*i+2] + w.w * xs[r][4*i+3];
    }
    g_k[(size_t)row * DD + j] = acc;
}

// ---------------- K3: Q = x_[:, T-1] @ q_w.T + q_b ----------------
__global__ void q_kernel(const float* __restrict__ W,
                         const float* __restrict__ bias) {
    __shared__ float xs[4][DD];
    int r = threadIdx.x >> 6, j = threadIdx.x & 63;
    int b = blockIdx.y;
    int n = blockIdx.x * 4 + r;
    if (n < NN)
        xs[r][j] = g_xn[(((size_t)b * TT + (TT - 1)) * NN + n) * DD + j];
    __syncthreads();
    if (n >= NN) return;
    float acc = bias[j];
    const float4* w4 = (const float4*)(W + (size_t)j * DD);
    #pragma unroll
    for (int i = 0; i < 16; i++) {
        float4 w = w4[i];
        acc += w.x * xs[r][4*i] + w.y * xs[r][4*i+1]
             + w.z * xs[r][4*i+2] + w.w * xs[r][4*i+3];
    }
    g_q[((size_t)b * NN + n) * DD + j] = acc;
}

// ---------------- K4: fused attention per (b, n0..n0+NT) ----------------
// dyn smem layout: sag[NT*TM] | q_s[NT*64] | w_s[WMAX] | red[256] | hist[256] | idx_s[WMAX] (u16)
#define ATTN_SMEM ((NT*TM + NT*DD + WMAX + 256 + 256) * 4 + WMAX * 2)

__global__ void attn_kernel(const float* __restrict__ stg,
                            const int* __restrict__ topk_p) {
    extern __shared__ float smf[];
    float* sag = smf;
    float* q_s = sag + NT * TM;
    float* w_s = q_s + NT * DD;
    float* red = w_s + WMAX;
    int*   hist = (int*)(red + 256);
    unsigned short* idx_s = (unsigned short*)(hist + 256);

    __shared__ unsigned sh_prefix;
    __shared__ int sh_rank;

    const int tid = threadIdx.x;
    const int b  = blockIdx.y;
    const int n0 = blockIdx.x * NT;

    const float* kb   = g_k  + (size_t)b * TM * DD;
    const float* xb   = g_xn + (size_t)b * TM * DD;
    const float* stgb = stg  + (size_t)b * NN * TM;

    // load q rows (zero-pad invalid)
    for (int i = tid; i < NT * DD; i += 256) {
        int r = i >> 6, c = i & 63;
        int n = n0 + r;
        q_s[i] = (n < NN) ? g_q[((size_t)b * NN + n) * DD + c] : 0.0f;
    }
    __syncthreads();

    // ---- phase 1: scores ----
    for (int tm = tid; tm < TM; tm += 256) {
        float acc[NT];
        #pragma unroll
        for (int r = 0; r < NT; r++) acc[r] = 0.0f;
        const float4* kr = (const float4*)(kb + (size_t)tm * DD);
        #pragma unroll
        for (int i = 0; i < 16; i++) {
            float4 kv = kr[i];
            #pragma unroll
            for (int r = 0; r < NT; r++) {
                acc[r] += kv.x * q_s[r*DD + 4*i]   + kv.y * q_s[r*DD + 4*i+1]
                        + kv.z * q_s[r*DD + 4*i+2] + kv.w * q_s[r*DD + 4*i+3];
            }
        }
        #pragma unroll
        for (int r = 0; r < NT; r++) {
            int n = n0 + r;
            if (n < NN) {
                float dg = acc[r] * SCALE;
                float sg = 1.0f / (1.0f + __expf(-dg));
                sag[r*TM + tm] = sg * stgb[(size_t)n * TM + tm] * SCALE;
            }
        }
    }
    __syncthreads();

    int tk = topk_p[0];
    int kk = (tk > 0) ? ((tk < 5) ? tk * NN : tk) : 0;

    // ---- phase 2: per-row select + softmax + aggregate ----
    for (int r = 0; r < NT; r++) {
        int n = n0 + r;
        if (n >= NN) break;                     // uniform
        float* row = sag + r * TM;

        // exact kk-th largest via 4-pass radix select on monotone bits
        unsigned thr_u = 0;
        if (kk > 0) {
            unsigned prefix = 0, pmask = 0;
            int rank = kk;
            for (int pass = 0; pass < 4; pass++) {
                int shift = 24 - 8 * pass;
                hist[tid] = 0;
                __syncthreads();
                for (int tm = tid; tm < TM; tm += 256) {
                    unsigned u = mono(row[tm]);
                    if ((u & pmask) == prefix)
                        atomicAdd(&hist[(u >> shift) & 255], 1);
                }
                __syncthreads();
                if (tid == 0) {
                    int c = 0, bin = 255;
                    for (; bin >= 0; bin--) {
                        c += hist[bin];
                        if (c >= rank) break;
                    }
                    sh_rank   = rank - (c - hist[bin]);
                    sh_prefix = prefix | ((unsigned)bin << shift);
                }
                __syncthreads();
                rank   = sh_rank;
                prefix = sh_prefix;
                pmask |= 0xFFu << shift;
                __syncthreads();
            }
            thr_u = prefix;
        }

        // max over kept
        float mx = -3.4e38f;
        for (int tm = tid; tm < TM; tm += 256) {
            float v = row[tm];
            if (kk == 0 || mono(v) > thr_u) mx = fmaxf(mx, v);
        }
        red[tid] = mx;
        __syncthreads();
        for (int s = 128; s > 0; s >>= 1) {
            if (tid < s) red[tid] = fmaxf(red[tid], red[tid + s]);
            __syncthreads();
        }
        float m = red[0];
        __syncthreads();

        // deterministic compaction: count -> scan -> ordered write
        int cntloc = 0;
        if (kk > 0) {
            for (int tm = tid; tm < TM; tm += 256)
                if (mono(row[tm]) > thr_u) cntloc++;
        }
        hist[tid] = cntloc;
        __syncthreads();
        for (int off = 1; off < 256; off <<= 1) {
            int v = (tid >= off) ? hist[tid - off] : 0;
            __syncthreads();
            hist[tid] += v;
            __syncthreads();
        }
        int total = hist[255];
        int base  = hist[tid] - cntloc;
        __syncthreads();

        bool compact = (kk > 0) && (total > 0) && (total <= WMAX);
        bool uniform_fb = (kk > 0) && (total == 0);   // all-ties fallback
        float ssum = 0.0f;
        if (compact) {
            int p = base;
            for (int tm = tid; tm < TM; tm += 256) {
                float v = row[tm];
                if (mono(v) > thr_u) {
                    float w = __expf(v - m);
                    w_s[p] = w;
                    idx_s[p] = (unsigned short)tm;
                    p++;
                    ssum += w;
                }
            }
        } else {
            for (int tm = tid; tm < TM; tm += 256) {
                float v = row[tm];
                float w;
                if (uniform_fb)                    w = 1.0f;
                else if (kk == 0 || mono(v) > thr_u) w = __expf(v - m);
                else                                w = 0.0f;
                row[tm] = w;
                ssum += w;
            }
        }
        red[tid] = ssum;
        __syncthreads();
        for (int s = 128; s > 0; s >>= 1) {
            if (tid < s) red[tid] += red[tid + s];
            __syncthreads();
        }
        float S = red[0];
        __syncthreads();

        // aggregate o = sum w * x_ ; 4 groups x 64 lanes
        int g = tid >> 6, lane = tid & 63;
        float acc = 0.0f;
        if (compact) {
            for (int j = g; j < total; j += 4)
                acc += w_s[j] * xb[(size_t)idx_s[j] * DD + lane];
        } else {
            for (int j = g; j < TM; j += 4)
                acc += row[j] * xb[(size_t)j * DD + lane];
        }
        red[tid] = acc;
        __syncthreads();
        if (tid < 64) {
            float o = red[lane] + red[64 + lane] + red[128 + lane] + red[192 + lane];
            float y = xb[((size_t)(TT - 1) * NN + n) * DD + lane];
            g_h[((size_t)b * NN + n) * DD + lane] = o / S + y;
        }
        __syncthreads();
    }
}

// ---------------- K5: FFN + residual, writes final output ----------------
#define FFN_ROWS 32
__global__ void ffn_kernel(const float* __restrict__ g,
                           const float* __restrict__ bb,
                           const float* __restrict__ w1,
                           const float* __restrict__ b1,
                           const float* __restrict__ w2,
                           const float* __restrict__ b2,
                           float* __restrict__ out, int rows) {
    __shared__ float z_s[DD], h_s[DD], a_s[256], red[DD];
    int tid = threadIdx.x;
    int row0 = blockIdx.x * FFN_ROWS;
    for (int rr = 0; rr < FFN_ROWS; rr++) {
        int row = row0 + rr;
        if (row >= rows) break;                 // uniform
        if (tid < DD) {
            float v = g_h[(size_t)row * DD + tid];
            h_s[tid] = v;
            red[tid] = v;
        }
        __syncthreads();
        if (tid < 32) {
            float s = red[tid] + red[tid + 32];
            #pragma unroll
            for (int o = 16; o > 0; o >>= 1) s += __shfl_xor_sync(0xFFFFFFFFu, s, o);
            if (tid == 0) red[0] = s;
        }
        __syncthreads();
        float mu = red[0] * (1.0f / DD);
        __syncthreads();
        if (tid < DD) {
            float d = h_s[tid] - mu;
            red[tid] = d * d;
        }
        __syncthreads();
        if (tid < 32) {
            float s = red[tid] + red[tid + 32];
            #pragma unroll
            for (int o = 16; o > 0; o >>= 1) s += __shfl_xor_sync(0xFFFFFFFFu, s, o);
            if (tid == 0) red[0] = s;
        }
        __syncthreads();
        float rstd = rsqrtf(red[0] * (1.0f / DD) + 1e-5f);
        if (tid < DD) z_s[tid] = (h_s[tid] - mu) * rstd * g[tid] + bb[tid];
        __syncthreads();
        // fc1 + relu : 256 threads, one output each
        {
            float a = b1[tid];
            const float4* w1r = (const float4*)(w1 + (size_t)tid * DD);
            #pragma unroll
            for (int i = 0; i < 16; i++) {
                float4 w = w1r[i];
                a += w.x * z_s[4*i] + w.y * z_s[4*i+1]
                   + w.z * z_s[4*i+2] + w.w * z_s[4*i+3];
            }
            a_s[tid] = fmaxf(a, 0.0f);
        }
        __syncthreads();
        // fc2 + residual
        if (tid < DD) {
            float o = b2[tid];
            const float4* w2r = (const float4*)(w2 + (size_t)tid * 256);
            #pragma unroll
            for (int j = 0; j < 64; j++) {
                float4 w = w2r[j];
                o += w.x * a_s[4*j] + w.y * a_s[4*j+1]
                   + w.z * a_s[4*j+2] + w.w * a_s[4*j+3];
            }
            out[(size_t)row * DD + tid] = h_s[tid] + o;
        }
        __syncthreads();
    }
}

// ---------------- launcher ----------------
extern "C" void kernel_launch(void* const* d_in, const int* in_sizes, int n_in,
                              void* d_out, int out_size) {
    const float* x    = (const float*)d_in[0];
    const float* stg  = (const float*)d_in[1];
    const int*   topk = (const int*)  d_in[2];
    const float* q_w  = (const float*)d_in[3];
    const float* q_b  = (const float*)d_in[4];
    const float* k_w  = (const float*)d_in[5];
    const float* k_b  = (const float*)d_in[6];
    const float* ln_g = (const float*)d_in[7];
    const float* ln_b = (const float*)d_in[8];
    const float* fg   = (const float*)d_in[9];
    const float* fb   = (const float*)d_in[10];
    const float* w1   = (const float*)d_in[11];
    const float* b1   = (const float*)d_in[12];
    const float* w2   = (const float*)d_in[13];
    const float* b2   = (const float*)d_in[14];
    float* out = (float*)d_out;

    const int rows_all = BB * TT * NN;   // 58944

    ln_kernel<<<rows_all / 8, 256>>>(x, ln_g, ln_b, rows_all);
    k_kernel<<<(rows_all + 3) / 4, 256>>>(k_w, k_b, rows_all);
    q_kernel<<<dim3((NN + 3) / 4, BB), 256>>>(q_w, q_b);

    cudaFuncSetAttribute(attn_kernel,
                         cudaFuncAttributeMaxDynamicSharedMemorySize, ATTN_SMEM);
    attn_kernel<<<dim3((NN + NT - 1) / NT, BB), 256, ATTN_SMEM>>>(stg, topk);

    ffn_kernel<<<(BB * NN + FFN_ROWS - 1) / FFN_ROWS, 256>>>(
        fg, fb, w1, b1, w2, b2, out, BB * NN);
}

// round 2
// speedup vs baseline: 1.3932x; 1.3932x over previous
#include <cuda_runtime.h>
#include <cuda_bf16.h>

#define BB   16
#define TT   12
#define NN   307
#define DD   64
#define TM   (TT*NN)      // 3684
#define NT   4            // n-rows per attention block
#define SCALE 0.125f      // 1/sqrt(64)

// ---------------- scratch (no runtime allocation allowed) ----------------
__device__ float g_xn[(size_t)BB*TT*NN*DD];   // layernormed x
__device__ float g_k [(size_t)BB*TT*NN*DD];   // K projection
__device__ float g_q [(size_t)BB*NN*DD];      // Q projection (from t = T-1)
__device__ float g_h [(size_t)BB*NN*DD];      // attention output + residual

__device__ __forceinline__ unsigned mono(float f) {
    unsigned u = __float_as_uint(f);
    return (u & 0x80000000u) ? ~u : (u | 0x80000000u);
}

__device__ __forceinline__ void gbar(int id) {
    asm volatile("bar.sync %0, 64;" :: "r"(id) : "memory");
}

// find the rank-th largest bin position in hist[0..nb), descending from top.
// out[0]=bin, out[1]=rank-within-bin, out[3]=scratch. 64-thread group collective.
__device__ __forceinline__ void find_bin(const int* hist, int nb, int rank,
                                         int lane, int barid, volatile int* out) {
    int chunk = nb >> 6; if (chunk == 0) chunk = 1;
    int hi = nb - chunk * lane;
    int lo = hi - chunk;
    if (hi < 0) hi = 0;
    if (lo < 0) lo = 0;
    int s = 0;
    for (int j = lo; j < hi; j++) s += hist[j];
    int incl = s;
    unsigned wl = lane & 31;
    #pragma unroll
    for (int o = 1; o < 32; o <<= 1) {
        int t = __shfl_up_sync(0xFFFFFFFFu, incl, o);
        if (wl >= o) incl += t;
    }
    if (lane == 31) out[3] = incl;
    gbar(barid);
    if (lane >= 32) incl += out[3];
    int excl = incl - s;
    if (excl < rank && rank <= incl) {
        int c = excl;
        for (int bin = hi - 1; bin >= lo; bin--) {
            c += hist[bin];
            if (c >= rank) { out[0] = bin; out[1] = rank - (c - hist[bin]); break; }
        }
    }
    gbar(barid);
}

// ---------------- K1: LayerNorm over d=64, one warp per row ----------------
__global__ void ln_kernel(const float* __restrict__ x,
                          const float* __restrict__ g,
                          const float* __restrict__ b, int rows) {
    int row  = blockIdx.x * 8 + (threadIdx.x >> 5);
    int lane = threadIdx.x & 31;
    if (row >= rows) return;
    const float2* xr = (const float2*)(x + (size_t)row * DD);
    float2 v = xr[lane];
    float s = v.x + v.y;
    #pragma unroll
    for (int o = 16; o > 0; o >>= 1) s += __shfl_xor_sync(0xFFFFFFFFu, s, o);
    float mu = s * (1.0f / DD);
    float dx = v.x - mu, dy = v.y - mu;
    float q = dx * dx + dy * dy;
    #pragma unroll
    for (int o = 16; o > 0; o >>= 1) q += __shfl_xor_sync(0xFFFFFFFFu, q, o);
    float rstd = rsqrtf(q * (1.0f / DD) + 1e-5f);
    float2 gg = ((const float2*)g)[lane];
    float2 bv = ((const float2*)b)[lane];
    float2 ov;
    ov.x = dx * rstd * gg.x + bv.x;
    ov.y = dy * rstd * gg.y + bv.y;
    ((float2*)(g_xn + (size_t)row * DD))[lane] = ov;
}

// ---------------- K2: K = x_ @ k_w.T + k_b ----------------
__global__ void k_kernel(const float* __restrict__ W,
                         const float* __restrict__ bias, int rows) {
    __shared__ float xs[4][DD];
    int r = threadIdx.x >> 6, j = threadIdx.x & 63;
    int row = blockIdx.x * 4 + r;
    if (row < rows) xs[r][j] = g_xn[(size_t)row * DD + j];
    __syncthreads();
    if (row >= rows) return;
    float acc = bias[j];
    const float4* w4 = (const float4*)(W + (size_t)j * DD);
    #pragma unroll
    for (int i = 0; i < 16; i++) {
        float4 w = w4[i];
        acc += w.x * xs[r][4*i] + w.y * xs[r][4*i+1]
             + w.z * xs[r][4*i+2] + w.w * xs[r][4*i+3];
    }
    g_k[(size_t)row * DD + j] = acc;
}

// ---------------- K3: Q = x_[:, T-1] @ q_w.T + q_b ----------------
__global__ void q_kernel(const float* __restrict__ W,
                         const float* __restrict__ bias) {
    __shared__ float xs[4][DD];
    int r = threadIdx.x >> 6, j = threadIdx.x & 63;
    int b = blockIdx.y;
    int n = blockIdx.x * 4 + r;
    if (n < NN)
        xs[r][j] = g_xn[(((size_t)b * TT + (TT - 1)) * NN + n) * DD + j];
    __syncthreads();
    if (n >= NN) return;
    float acc = bias[j];
    const float4* w4 = (const float4*)(W + (size_t)j * DD);
    #pragma unroll
    for (int i = 0; i < 16; i++) {
        float4 w = w4[i];
        acc += w.x * xs[r][4*i] + w.y * xs[r][4*i+1]
             + w.z * xs[r][4*i+2] + w.w * xs[r][4*i+3];
    }
    g_q[((size_t)b * NN + n) * DD + j] = acc;
}

// ---------------- K4: fused attention per (b, n0..n0+NT) ----------------
// dyn smem (floats): sag[NT*TM] | q_s[NT*DD] | B[NT*2048] (int) |
//                    h2[NT*256] (int) | si[NT*8] (int) | sf[NT*4]
#define ATTN_SMEM_FLOATS (NT*TM + NT*DD + NT*2048 + NT*256 + NT*8 + NT*4)
#define ATTN_SMEM (ATTN_SMEM_FLOATS * 4)

__global__ void attn_kernel(const float* __restrict__ stg,
                            const int* __restrict__ topk_p) {
    extern __shared__ float sm[];
    float* sag = sm;
    float* q_s = sag + NT * TM;
    int*   B   = (int*)(q_s + NT * DD);
    int*   h2  = B + NT * 2048;
    int*   si  = h2 + NT * 256;
    float* sf  = (float*)(si + NT * 8);

    const int tid = threadIdx.x;
    const int b  = blockIdx.y;
    const int n0 = blockIdx.x * NT;

    const float* kb   = g_k  + (size_t)b * TM * DD;
    const float* xb   = g_xn + (size_t)b * TM * DD;
    const float* stgb = stg  + (size_t)b * NN * TM;

    // load q rows (zero-pad invalid)
    for (int i = tid; i < NT * DD; i += 256) {
        int r = i >> 6, c = i & 63;
        int n = n0 + r;
        q_s[i] = (n < NN) ? g_q[((size_t)b * NN + n) * DD + c] : 0.0f;
    }
    __syncthreads();

    // ---- phase 1: scores (all 256 threads over tm) ----
    for (int tm = tid; tm < TM; tm += 256) {
        float acc[NT];
        #pragma unroll
        for (int r = 0; r < NT; r++) acc[r] = 0.0f;
        const float4* kr = (const float4*)(kb + (size_t)tm * DD);
        #pragma unroll
        for (int i = 0; i < 16; i++) {
            float4 kv = kr[i];
            #pragma unroll
            for (int r = 0; r < NT; r++) {
                acc[r] += kv.x * q_s[r*DD + 4*i]   + kv.y * q_s[r*DD + 4*i+1]
                        + kv.z * q_s[r*DD + 4*i+2] + kv.w * q_s[r*DD + 4*i+3];
            }
        }
        #pragma unroll
        for (int r = 0; r < NT; r++) {
            int n = n0 + r;
            if (n < NN) {
                float dg = acc[r] * SCALE;
                float sg = 1.0f / (1.0f + __expf(-dg));
                sag[r*TM + tm] = sg * stgb[(size_t)n * TM + tm] * SCALE;
            }
        }
    }
    __syncthreads();

    int tk = topk_p[0];
    int kk = (tk > 0) ? ((tk < 5) ? tk * NN : tk) : 0;
    if (kk > TM) kk = TM;

    // ---- phase 2: one 64-thread group per row, all rows in parallel ----
    const int g     = tid >> 6;
    const int lane  = tid & 63;
    const int barid = g + 1;
    const int n     = n0 + g;

    if (n < NN) {
        float* row = sag + g * TM;
        int*   hist = B  + g * 2048;
        int*   hb   = h2 + g * 256;
        unsigned short* cand = (unsigned short*)hist;   // reuse after pass1
        volatile int*   gi = si + g * 8;
        volatile float* gf = sf + g * 4;

        unsigned thr_u = 0;
        if (kk > 0) {
            // pass 1: 11-bit histogram on bits [30:20] of mono
            for (int i = lane; i < 2048; i += 64) hist[i] = 0;
            gbar(barid);
            for (int tm = lane; tm < TM; tm += 64) {
                unsigned u = mono(row[tm]);
                atomicAdd(&hist[(u >> 20) & 0x7FF], 1);
            }
            gbar(barid);
            find_bin(hist, 2048, kk, lane, barid, gi);
            int bin  = gi[0];
            int rank = gi[1];
            unsigned prefix = (0x800u | (unsigned)bin) << 20;
            unsigned pmask  = 0xFFF00000u;
            if (lane == 0) gi[2] = 0;
            gbar(barid);
            // compact candidates (reuses hist storage as u16[4096] >= TM)
            for (int tm = lane; tm < TM; tm += 64) {
                unsigned u = mono(row[tm]);
                if ((u & pmask) == prefix) {
                    int p = atomicAdd((int*)(si + g*8 + 2), 1);
                    cand[p] = (unsigned short)tm;
                }
            }
            gbar(barid);
            int nc = gi[2];
            // refine passes over candidates only: bits [19:12], [11:4], [3:0]
            #pragma unroll
            for (int p = 0; p < 3; p++) {
                const int sh = (p == 0) ? 12 : (p == 1) ? 4 : 0;
                const int nb = (p == 2) ? 16 : 256;
                const unsigned fm = (p == 2) ? 0xFu : 0xFFu;
                for (int i = lane; i < nb; i += 64) hb[i] = 0;
                gbar(barid);
                for (int i = lane; i < nc; i += 64) {
                    unsigned u = mono(row[cand[i]]);
                    if ((u & pmask) == prefix)
                        atomicAdd(&hb[(u >> sh) & fm], 1);
                }
                gbar(barid);
                find_bin(hb, nb, rank, lane, barid, gi);
                int b2 = gi[0];
                rank = gi[1];
                prefix |= (unsigned)b2 << sh;
                pmask  |= fm << sh;
                gbar(barid);
            }
            thr_u = prefix;
        }

        // max over kept
        float mx = -3.4e38f;
        for (int tm = lane; tm < TM; tm += 64) {
            float v = row[tm];
            if (kk == 0 || mono(v) > thr_u) mx = fmaxf(mx, v);
        }
        #pragma unroll
        for (int o = 16; o > 0; o >>= 1)
            mx = fmaxf(mx, __shfl_xor_sync(0xFFFFFFFFu, mx, o));
        if ((lane & 31) == 0) gf[lane >> 5] = mx;
        gbar(barid);
        float m = fmaxf(gf[0], gf[1]);

        // exp weights in place + sum
        float ss = 0.0f;
        for (int tm = lane; tm < TM; tm += 64) {
            float v = row[tm];
            float w = 0.0f;
            if (kk == 0 || mono(v) > thr_u) w = __expf(v - m);
            row[tm] = w;
            ss += w;
        }
        #pragma unroll
        for (int o = 16; o > 0; o >>= 1)
            ss += __shfl_xor_sync(0xFFFFFFFFu, ss, o);
        if ((lane & 31) == 0) gf[lane >> 5] = ss;
        gbar(barid);
        float S = gf[0] + gf[1];
        if (S == 0.0f) {    // degenerate all-ties: uniform softmax
            for (int tm = lane; tm < TM; tm += 64) row[tm] = 1.0f;
            S = (float)TM;
        }
        if (lane == 0) gf[2] = 1.0f / S;
    }
    __syncthreads();

    // ---- phase 3: dense aggregation, all 256 threads share x rows ----
    {
        const int col = tid & 15;   // float4 column within d=64
        const int tl  = tid >> 4;   // 16 tm stripes
        float4 acc[NT];
        #pragma unroll
        for (int r = 0; r < NT; r++) acc[r] = make_float4(0.f, 0.f, 0.f, 0.f);
        const float4* xb4 = (const float4*)xb;
        #pragma unroll 4
        for (int tm = tl; tm < TM; tm += 16) {
            float4 xv = xb4[tm * 16 + col];
            #pragma unroll
            for (int r = 0; r < NT; r++) {
                float w = sag[r * TM + tm];
                acc[r].x += w * xv.x;
                acc[r].y += w * xv.y;
                acc[r].z += w * xv.z;
                acc[r].w += w * xv.w;
            }
        }
        float4* red4 = (float4*)B;   // reuse select scratch (16KB needed, 32KB avail)
        #pragma unroll
        for (int r = 0; r < NT; r++)
            red4[(r * 16 + tl) * 16 + col] = acc[r];
        __syncthreads();
        if (tid < 64) {
            int r = tid >> 4, c = tid & 15;
            int nn = n0 + r;
            if (nn < NN) {
                float4 s = make_float4(0.f, 0.f, 0.f, 0.f);
                #pragma unroll
                for (int t2 = 0; t2 < 16; t2++) {
                    float4 v = red4[(r * 16 + t2) * 16 + c];
                    s.x += v.x; s.y += v.y; s.z += v.z; s.w += v.w;
                }
                float inv = sf[r * 4 + 2];
                float4 y = ((const float4*)(xb + ((size_t)(TT-1) * NN + nn) * DD))[c];
                float4 o;
                o.x = s.x * inv + y.x;
                o.y = s.y * inv + y.y;
                o.z = s.z * inv + y.z;
                o.w = s.w * inv + y.w;
                ((float4*)(g_h + ((size_t)b * NN + nn) * DD))[c] = o;
            }
        }
    }
}

// ---------------- K5: FFN + residual, one row per block ----------------
__global__ void ffn_kernel(const float* __restrict__ g,
                           const float* __restrict__ bb,
                           const float* __restrict__ w1,
                           const float* __restrict__ b1,
                           const float* __restrict__ w2,
                           const float* __restrict__ b2,
                           float* __restrict__ out) {
    __shared__ float z_s[DD], h_s[DD], a_s[256], redm[256];
    __shared__ float c1[2], c2[2];
    const int tid = threadIdx.x;
    const int row = blockIdx.x;

    float v = 0.0f;
    if (tid < DD) {
        v = g_h[(size_t)row * DD + tid];
        h_s[tid] = v;
    }
    float s1 = v, s2 = v * v;
    #pragma unroll
    for (int o = 16; o > 0; o >>= 1) {
        s1 += __shfl_xor_sync(0xFFFFFFFFu, s1, o);
        s2 += __shfl_xor_sync(0xFFFFFFFFu, s2, o);
    }
    if (tid < DD && (tid & 31) == 0) { c1[tid >> 5] = s1; c2[tid >> 5] = s2; }
    __syncthreads();
    float mu  = (c1[0] + c1[1]) * (1.0f / DD);
    float var = (c2[0] + c2[1]) * (1.0f / DD) - mu * mu;
    float rstd = rsqrtf(var + 1e-5f);
    if (tid < DD) z_s[tid] = (h_s[tid] - mu) * rstd * g[tid] + bb[tid];
    __syncthreads();

    // fc1 + relu: each thread one of 256 outputs
    {
        float a = b1[tid];
        const float4* w1r = (const float4*)(w1 + (size_t)tid * DD);
        #pragma unroll
        for (int i = 0; i < 16; i++) {
            float4 w = w1r[i];
            a += w.x * z_s[4*i] + w.y * z_s[4*i+1]
               + w.z * z_s[4*i+2] + w.w * z_s[4*i+3];
        }
        a_s[tid] = fmaxf(a, 0.0f);
    }
    __syncthreads();

    // fc2: 4 partial segments per output column
    {
        int j = tid & 63, seg = tid >> 6;
        float p = (seg == 0) ? b2[j] : 0.0f;
        const float4* w2r = (const float4*)(w2 + (size_t)j * 256 + seg * 64);
        const float*  ar  = a_s + seg * 64;
        #pragma unroll
        for (int i = 0; i < 16; i++) {
            float4 w = w2r[i];
            p += w.x * ar[4*i] + w.y * ar[4*i+1]
               + w.z * ar[4*i+2] + w.w * ar[4*i+3];
        }
        redm[tid] = p;
    }
    __syncthreads();
    if (tid < DD) {
        float o = redm[tid] + redm[tid + 64] + redm[tid + 128] + redm[tid + 192];
        out[(size_t)row * DD + tid] = h_s[tid] + o;
    }
}

// ---------------- launcher ----------------
extern "C" void kernel_launch(void* const* d_in, const int* in_sizes, int n_in,
                              void* d_out, int out_size) {
    const float* x    = (const float*)d_in[0];
    const float* stg  = (const float*)d_in[1];
    const int*   topk = (const int*)  d_in[2];
    const float* q_w  = (const float*)d_in[3];
    const float* q_b  = (const float*)d_in[4];
    const float* k_w  = (const float*)d_in[5];
    const float* k_b  = (const float*)d_in[6];
    const float* ln_g = (const float*)d_in[7];
    const float* ln_b = (const float*)d_in[8];
    const float* fg   = (const float*)d_in[9];
    const float* fb   = (const float*)d_in[10];
    const float* w1   = (const float*)d_in[11];
    const float* b1   = (const float*)d_in[12];
    const float* w2   = (const float*)d_in[13];
    const float* b2   = (const float*)d_in[14];
    float* out = (float*)d_out;

    const int rows_all = BB * TT * NN;   // 58944

    ln_kernel<<<rows_all / 8, 256>>>(x, ln_g, ln_b, rows_all);
    k_kernel<<<(rows_all + 3) / 4, 256>>>(k_w, k_b, rows_all);
    q_kernel<<<dim3((NN + 3) / 4, BB), 256>>>(q_w, q_b);

    cudaFuncSetAttribute(attn_kernel,
                         cudaFuncAttributeMaxDynamicSharedMemorySize, ATTN_SMEM);
    attn_kernel<<<dim3((NN + NT - 1) / NT, BB), 256, ATTN_SMEM>>>(stg, topk);

    ffn_kernel<<<BB * NN, 256>>>(fg, fb, w1, b1, w2, b2, out);
}